// round 1
// baseline (speedup 1.0000x reference)
#include <cuda_runtime.h>
#include <math.h>

// Problem constants
#define BB    256     // batch
#define TT    64      // time steps
#define INS   600     // input size
#define HH    1000    // hidden
#define G4    4000    // 4*hidden

// ---------------------------------------------------------------------------
// Scratch (static __device__ arrays — no allocation allowed in kernel_launch)
// ---------------------------------------------------------------------------
__device__ float g_X1[(size_t)BB * TT * G4];   // x-part of gates for all t: row (b*64+t), 262 MB
__device__ float g_A1[G4 * HH];                // W_ih1[:,600:1600] + W_hh1
__device__ float g_Acat[G4 * 2 * HH];          // [ W_ih2[:,600:1600] | W_ih2[:,1600:2600]+W_hh2 ]
__device__ float g_bias1[G4];                  // b_ih1 + b_hh1
__device__ float g_bias2[G4];                  // b_ih2 + b_hh2
__device__ float g_G[BB * G4];                 // gates / M1 buffer
__device__ float g_H12[BB * 2 * HH];           // [h1 | h2] per batch row (stride 2000)
__device__ float g_c1[BB * HH];
__device__ float g_c2[BB * HH];
__device__ float g_Z[BB * 2 * HH];             // [h1 | topic]

// ---------------------------------------------------------------------------
// Weight prep: combine recurrent weights & biases (cheap, once per launch)
// ---------------------------------------------------------------------------
__global__ void prep_weights(const float* __restrict__ W_ih1, const float* __restrict__ W_hh1,
                             const float* __restrict__ b_ih1, const float* __restrict__ b_hh1,
                             const float* __restrict__ W_ih2, const float* __restrict__ W_hh2,
                             const float* __restrict__ b_ih2, const float* __restrict__ b_hh2)
{
    int idx = blockIdx.x * blockDim.x + threadIdx.x;
    const int total = G4 * 2 * HH;
    for (int i = idx; i < total; i += gridDim.x * blockDim.x) {
        int r = i / (2 * HH);
        int c = i % (2 * HH);
        float v;
        if (c < HH) {
            v = W_ih2[(size_t)r * 2600 + 600 + c];
            // also fill A1 on this half of the index space
            g_A1[(size_t)r * HH + c] = W_ih1[(size_t)r * 1600 + 600 + c] + W_hh1[(size_t)r * HH + c];
        } else {
            int cc = c - HH;
            v = W_ih2[(size_t)r * 2600 + 1600 + cc] + W_hh2[(size_t)r * HH + cc];
        }
        g_Acat[i] = v;
    }
    if (idx < G4) {
        g_bias1[idx] = b_ih1[idx] + b_hh1[idx];
        g_bias2[idx] = b_ih2[idx] + b_hh2[idx];
    }
}

__global__ void init_state()
{
    int idx = blockIdx.x * blockDim.x + threadIdx.x;   // 512000 threads
    if (idx < BB * 2 * HH) g_H12[idx] = 0.f;
    if (idx < BB * HH) { g_c1[idx] = 0.f; g_c2[idx] = 0.f; }
}

// ---------------------------------------------------------------------------
// SGEMM (NT): C[M,N] = A[M,K] * B[N,K]^T  (+ Cin) (+ bias[N])
// 64x64 tile, BK=8, 128 threads, 8x4 per-thread register tile.
// Requirements: M % 64 == 0, K % 8 == 0, lda/ldb % 4 == 0 (all calls satisfy).
// ---------------------------------------------------------------------------
__global__ __launch_bounds__(128) void sgemm_nt(
    int M, int N, int K,
    const float* __restrict__ A, int lda,
    const float* __restrict__ Bm, int ldb,
    float* __restrict__ C, int ldc,
    const float* __restrict__ Cin, int ldcin,
    const float* __restrict__ bias)
{
    __shared__ float As[8][64];
    __shared__ float Bs[8][64];

    const int tid = threadIdx.x;
    const int bm = blockIdx.x * 64;
    const int bn = blockIdx.y * 64;

    const int tr = tid >> 4;         // 0..7  -> rows tr*8 .. tr*8+7
    const int tc = tid & 15;         // 0..15 -> cols tc*4 .. tc*4+3

    const int lrow = tid >> 1;       // 0..63 (tile row for A, tile col for B)
    const int lcol = (tid & 1) * 4;  // 0 or 4 (k offset)

    const float* Ap = A + (size_t)(bm + lrow) * lda + lcol;
    const int bg = bn + lrow;
    const float* Bp = Bm + (size_t)bg * ldb + lcol;
    const bool bok = (bg < N);

    float acc[8][4];
#pragma unroll
    for (int i = 0; i < 8; i++)
#pragma unroll
        for (int j = 0; j < 4; j++) acc[i][j] = 0.f;

    for (int k0 = 0; k0 < K; k0 += 8) {
        float4 av = *reinterpret_cast<const float4*>(Ap + k0);
        float4 bv = bok ? *reinterpret_cast<const float4*>(Bp + k0)
                        : make_float4(0.f, 0.f, 0.f, 0.f);
        As[lcol + 0][lrow] = av.x; As[lcol + 1][lrow] = av.y;
        As[lcol + 2][lrow] = av.z; As[lcol + 3][lrow] = av.w;
        Bs[lcol + 0][lrow] = bv.x; Bs[lcol + 1][lrow] = bv.y;
        Bs[lcol + 2][lrow] = bv.z; Bs[lcol + 3][lrow] = bv.w;
        __syncthreads();
#pragma unroll
        for (int k = 0; k < 8; k++) {
            float a[8], b[4];
#pragma unroll
            for (int i = 0; i < 8; i++) a[i] = As[k][tr * 8 + i];
#pragma unroll
            for (int j = 0; j < 4; j++) b[j] = Bs[k][tc * 4 + j];
#pragma unroll
            for (int i = 0; i < 8; i++)
#pragma unroll
                for (int j = 0; j < 4; j++)
                    acc[i][j] = fmaf(a[i], b[j], acc[i][j]);
        }
        __syncthreads();
    }

#pragma unroll
    for (int i = 0; i < 8; i++) {
        int r = bm + tr * 8 + i;
#pragma unroll
        for (int j = 0; j < 4; j++) {
            int c = bn + tc * 4 + j;
            if (c < N) {
                float v = acc[i][j];
                if (Cin)  v += Cin[(size_t)r * ldcin + c];
                if (bias) v += bias[c];
                C[(size_t)r * ldc + c] = v;
            }
        }
    }
}

// ---------------------------------------------------------------------------
// Fused LSTM pointwise: gates (B x 4000, order i|f|g|o) + bias -> h (into H12
// at column offset h_off), c updated in place.
// ---------------------------------------------------------------------------
__global__ void lstm_ew(const float* __restrict__ Gt, const float* __restrict__ bias,
                        float* __restrict__ c, int h_off)
{
    int idx = blockIdx.x * blockDim.x + threadIdx.x;
    if (idx >= BB * HH) return;
    int b = idx / HH, j = idx % HH;
    const float* g = Gt + (size_t)b * G4;
    float gi = g[j]          + bias[j];
    float gf = g[j + HH]     + bias[j + HH];
    float gg = g[j + 2 * HH] + bias[j + 2 * HH];
    float go = g[j + 3 * HH] + bias[j + 3 * HH];
    float si = 1.f / (1.f + expf(-gi));
    float sf = 1.f / (1.f + expf(-gf));
    float so = 1.f / (1.f + expf(-go));
    float tg = tanhf(gg);
    float cn = sf * c[idx] + si * tg;
    c[idx] = cn;
    g_H12[(size_t)b * (2 * HH) + h_off + j] = so * tanhf(cn);
}

// ---------------------------------------------------------------------------
// Epilogue helpers
// ---------------------------------------------------------------------------
__global__ void build_z()
{
    int idx = blockIdx.x * blockDim.x + threadIdx.x;   // 512000
    if (idx >= BB * 2 * HH) return;
    int b = idx / (2 * HH), j = idx % (2 * HH);
    g_Z[idx] = (j < HH) ? g_H12[(size_t)b * (2 * HH) + j] : 0.f;
}

__global__ void scatter_topic(const int* __restrict__ h)
{
    int idx = blockIdx.x * blockDim.x + threadIdx.x;   // 1280
    if (idx >= BB * 5) return;
    int b = idx / 5;
    int t = h[idx];
    if (t >= 0 && t < HH)
        g_Z[(size_t)b * (2 * HH) + HH + t] = 1.0f;
}

// In-place softmax over dim 0 (256 rows) of out[256,1000]; one block per column.
__global__ void softmax_dim0(float* __restrict__ out)
{
    __shared__ float red[BB];
    int j = blockIdx.x;         // 0..999
    int b = threadIdx.x;        // 0..255
    float v = out[(size_t)b * HH + j];
    red[b] = v;
    __syncthreads();
    for (int s = 128; s > 0; s >>= 1) {
        if (b < s) red[b] = fmaxf(red[b], red[b + s]);
        __syncthreads();
    }
    float mx = red[0];
    __syncthreads();
    float e = expf(v - mx);
    red[b] = e;
    __syncthreads();
    for (int s = 128; s > 0; s >>= 1) {
        if (b < s) red[b] += red[b + s];
        __syncthreads();
    }
    out[(size_t)b * HH + j] = e / red[0];
}

// Write (h1, c1, h2, c2) after the softmax block in d_out.
__global__ void copy_states(float* __restrict__ out)
{
    int idx = blockIdx.x * blockDim.x + threadIdx.x;   // 256000
    if (idx >= BB * HH) return;
    int b = idx / HH, j = idx % HH;
    out[256000 + idx]  = g_H12[(size_t)b * (2 * HH) + j];        // h1
    out[512000 + idx]  = g_c1[idx];                              // c1
    out[768000 + idx]  = g_H12[(size_t)b * (2 * HH) + HH + j];   // h2
    out[1024000 + idx] = g_c2[idx];                              // c2
}

// ---------------------------------------------------------------------------
// Launch (graph-capturable: kernel launches only)
// ---------------------------------------------------------------------------
extern "C" void kernel_launch(void* const* d_in, const int* in_sizes, int n_in,
                              void* d_out, int out_size)
{
    const float* input = (const float*)d_in[0];   // (256, 64, 600)
    const int*   h     = (const int*)  d_in[1];   // (256, 5)
    const float* W_ih1 = (const float*)d_in[2];
    const float* W_hh1 = (const float*)d_in[3];
    const float* b_ih1 = (const float*)d_in[4];
    const float* b_hh1 = (const float*)d_in[5];
    const float* W_ih2 = (const float*)d_in[6];
    const float* W_hh2 = (const float*)d_in[7];
    const float* b_ih2 = (const float*)d_in[8];
    const float* b_hh2 = (const float*)d_in[9];
    const float* W1    = (const float*)d_in[10];
    const float* b1    = (const float*)d_in[11];
    const float* W2    = (const float*)d_in[12];
    const float* b2    = (const float*)d_in[13];
    float* out = (float*)d_out;

    float *X1, *A1, *Acat, *bias1, *bias2, *Gp, *H12, *c1, *c2, *Z;
    cudaGetSymbolAddress((void**)&X1,    g_X1);
    cudaGetSymbolAddress((void**)&A1,    g_A1);
    cudaGetSymbolAddress((void**)&Acat,  g_Acat);
    cudaGetSymbolAddress((void**)&bias1, g_bias1);
    cudaGetSymbolAddress((void**)&bias2, g_bias2);
    cudaGetSymbolAddress((void**)&Gp,    g_G);
    cudaGetSymbolAddress((void**)&H12,   g_H12);
    cudaGetSymbolAddress((void**)&c1,    g_c1);
    cudaGetSymbolAddress((void**)&c2,    g_c2);
    cudaGetSymbolAddress((void**)&Z,     g_Z);

    // Weight prep + state init (independent of the big X1 GEMM)
    prep_weights<<<512, 256>>>(W_ih1, W_hh1, b_ih1, b_hh1, W_ih2, W_hh2, b_ih2, b_hh2);
    init_state<<<2000, 256>>>();

    // Parallel prologue: X1[b*64+t, :] = input[b,t,:] @ W_ih1[:, :600]^T
    sgemm_nt<<<dim3(16384 / 64, 63), 128>>>(
        16384, G4, INS, input, INS, W_ih1, 1600, X1, G4, nullptr, 0, nullptr);

    // Serial recurrence
    for (int t = 0; t < TT; t++) {
        // gates1 = X1[:, t] + h1 @ A1^T
        sgemm_nt<<<dim3(4, 63), 128>>>(
            BB, G4, HH, H12, 2 * HH, A1, HH, Gp, G4,
            X1 + (size_t)t * G4, TT * G4, nullptr);
        lstm_ew<<<1000, 256>>>(Gp, bias1, c1, /*h_off=*/0);

        // gates2 = [h1|h2] @ Acat^T
        sgemm_nt<<<dim3(4, 63), 128>>>(
            BB, G4, 2 * HH, H12, 2 * HH, Acat, 2 * HH, Gp, G4,
            nullptr, 0, nullptr);
        lstm_ew<<<1000, 256>>>(Gp, bias2, c2, /*h_off=*/HH);
    }

    // Epilogue: topic scatter + MLP + softmax(dim=0)
    build_z<<<2000, 256>>>();
    scatter_topic<<<5, 256>>>(h);
    sgemm_nt<<<dim3(4, 63), 128>>>(
        BB, G4, 2 * HH, Z, 2 * HH, W1, 2 * HH, Gp, G4, nullptr, 0, b1);
    sgemm_nt<<<dim3(4, 16), 128>>>(
        BB, HH, G4, Gp, G4, W2, G4, out, HH, nullptr, 0, b2);
    softmax_dim0<<<1000, 256>>>(out);

    if (out_size >= 1280000)
        copy_states<<<1000, 256>>>(out);
}

// round 3
// speedup vs baseline: 2.0065x; 2.0065x over previous
#include <cuda_runtime.h>
#include <cuda_bf16.h>
#include <math.h>
#include <stdint.h>

// ---------------------------------------------------------------------------
// Problem constants
// ---------------------------------------------------------------------------
#define BB    256     // batch
#define TT    64      // time steps
#define INS   600     // input size
#define HH    1000    // hidden
#define G4    4000    // 4*hidden
#define MP    4096    // padded gate-row count

// Stacked-K (3-pass bf16 split): K3 = 3 * Kpad.
// A-side stacking [hi|hi|lo], B-side [hi|lo|hi] -> passes hi*hi + hi*lo + lo*hi.
#define KP_X   640
#define K3_X   1920
#define KP_H1  1024
#define K3_H1  3072
#define KP_HH  2048
#define K3_HH  6144
#define KP_M1  4096
#define K3_M1  12288
#define NX     16384   // prologue N = T*B (row n = t*256 + b)

// ---------------------------------------------------------------------------
// Static device scratch
// ---------------------------------------------------------------------------
__device__ __align__(128) __nv_bfloat16 g_Wxst [(size_t)MP * K3_X];   // gate-permuted
__device__ __align__(128) __nv_bfloat16 g_A1st [(size_t)MP * K3_H1];  // gate-permuted
__device__ __align__(128) __nv_bfloat16 g_Acatst[(size_t)MP * K3_HH]; // gate-permuted
__device__ __align__(128) __nv_bfloat16 g_W1st [(size_t)MP * K3_HH];
__device__ __align__(128) __nv_bfloat16 g_W2st [(size_t)1024 * K3_M1];
__device__ __align__(128) __nv_bfloat16 g_Xst  [(size_t)NX * K3_X];
__device__ __align__(128) __nv_bfloat16 g_H1st [BB * K3_H1];
__device__ __align__(128) __nv_bfloat16 g_H12st[BB * K3_HH];
__device__ __align__(128) __nv_bfloat16 g_Zst  [BB * K3_HH];
__device__ __align__(128) __nv_bfloat16 g_M1st [BB * K3_M1];

__device__ __align__(128) float g_X1[(size_t)MP * NX];  // x-part of gates1 (perm rows), col = t*256+b
__device__ __align__(128) float g_C1[MP * BB];          // layer1 out [row][b]
__device__ __align__(128) float g_C2[1024 * BB];        // layer2 out [row][b]
__device__ __align__(128) float g_c1[BB * HH];          // cell state [b][j]
__device__ __align__(128) float g_c2[BB * HH];
__device__ __align__(128) float g_h1f[BB * HH];         // h fp32 [b][j]
__device__ __align__(128) float g_h2f[BB * HH];
__device__ __align__(16)  float g_bias1[MP];            // gate-permuted
__device__ __align__(16)  float g_bias2[MP];

// ---------------------------------------------------------------------------
// Helpers
// ---------------------------------------------------------------------------
__device__ __forceinline__ uint32_t smem_u32(const void* p) {
    uint32_t a;
    asm("{ .reg .u64 t; cvta.to.shared.u64 t, %1; cvt.u32.u64 %0, t; }" : "=r"(a) : "l"(p));
    return a;
}

__device__ __forceinline__ void ldm_x4(uint32_t& r0, uint32_t& r1, uint32_t& r2, uint32_t& r3,
                                       uint32_t addr) {
    asm volatile("ldmatrix.sync.aligned.m8n8.x4.shared.b16 {%0,%1,%2,%3}, [%4];"
        : "=r"(r0), "=r"(r1), "=r"(r2), "=r"(r3) : "r"(addr));
}

__device__ __forceinline__ void mma16816(float* d, const uint32_t* a, const uint32_t* b) {
    asm volatile(
        "mma.sync.aligned.m16n8k16.row.col.f32.bf16.bf16.f32 "
        "{%0,%1,%2,%3}, {%4,%5,%6,%7}, {%8,%9}, {%0,%1,%2,%3};"
        : "+f"(d[0]), "+f"(d[1]), "+f"(d[2]), "+f"(d[3])
        : "r"(a[0]), "r"(a[1]), "r"(a[2]), "r"(a[3]), "r"(b[0]), "r"(b[1]));
}

__device__ __forceinline__ void split_bf16(float v, __nv_bfloat16& hi, __nv_bfloat16& lo) {
    hi = __float2bfloat16(v);
    lo = __float2bfloat16(v - __bfloat162float(hi));
}

// ---------------------------------------------------------------------------
// Weight conversion: fp32 -> stacked bf16 [hi | hi | lo] (A-operand side).
// perm != 0: output row r corresponds to source row (r&3)*1000 + (r>>2)
// (gate-interleaved order i,f,g,o per hidden unit).
// ---------------------------------------------------------------------------
__global__ void cvt_weight(const float* __restrict__ src, int src_ld,
                           const float* __restrict__ add, int add_ld,
                           __nv_bfloat16* __restrict__ dst, int kpad,
                           int slot, int cpad, int C, int R, int Rpad, int perm)
{
    int stride = gridDim.x * blockDim.x;
    int total = Rpad * cpad;
    int k3 = 3 * kpad;
    for (int i = blockIdx.x * blockDim.x + threadIdx.x; i < total; i += stride) {
        int r = i / cpad, c = i % cpad;
        int sr; bool ok;
        if (perm) { int j = r >> 2, g = r & 3; sr = g * 1000 + j; ok = (j < 1000); }
        else      { sr = r; ok = (r < R); }
        float v = 0.f;
        if (ok && c < C) {
            v = src[(size_t)sr * src_ld + c];
            if (add) v += add[(size_t)sr * add_ld + c];
        }
        __nv_bfloat16 hi, lo; split_bf16(v, hi, lo);
        size_t base = (size_t)r * k3 + slot + c;
        dst[base]            = hi;
        dst[base + kpad]     = hi;
        dst[base + 2 * kpad] = lo;
    }
}

// Input x -> stacked [hi | lo | hi] (B-operand side); row n = t*256+b
__global__ void cvt_x(const float* __restrict__ input)
{
    int stride = gridDim.x * blockDim.x;
    const int total = NX * KP_X;
    for (int i = blockIdx.x * blockDim.x + threadIdx.x; i < total; i += stride) {
        int n = i / KP_X, c = i % KP_X;
        int t = n >> 8, b = n & 255;
        float v = (c < INS) ? input[((size_t)b * TT + t) * INS + c] : 0.f;
        __nv_bfloat16 hi, lo; split_bf16(v, hi, lo);
        size_t base = (size_t)n * K3_X + c;
        g_Xst[base]            = hi;
        g_Xst[base + KP_X]     = lo;
        g_Xst[base + 2 * KP_X] = hi;
    }
}

__global__ void prep_bias(const float* b_ih1, const float* b_hh1,
                          const float* b_ih2, const float* b_hh2)
{
    int i = blockIdx.x * blockDim.x + threadIdx.x;   // 0..4095
    if (i < MP) {
        int j = i >> 2, g = i & 3;
        int sr = g * 1000 + j;
        float v1 = 0.f, v2 = 0.f;
        if (j < 1000) {
            v1 = b_ih1[sr] + b_hh1[sr];
            v2 = b_ih2[sr] + b_hh2[sr];
        }
        g_bias1[i] = v1;
        g_bias2[i] = v2;
    }
}

__global__ void zero_state()
{
    int stride = gridDim.x * blockDim.x;
    int i0 = blockIdx.x * blockDim.x + threadIdx.x;
    __nv_bfloat16 z = __float2bfloat16(0.f);
    for (int i = i0; i < BB * HH; i += stride) { g_c1[i] = 0.f; g_c2[i] = 0.f; }
    for (int i = i0; i < BB * K3_H1; i += stride) g_H1st[i] = z;
    for (int i = i0; i < BB * K3_HH; i += stride) g_H12st[i] = z;
}

// ---------------------------------------------------------------------------
// mma.sync GEMM: C[M,N] = A[Mpad,K3] @ B[Npad,K3]^T  (bf16 in, fp32 out)
//   CTA tile 128 x BN, K-chunk 64, double-buffered smem, 8 warps.
//   MODE 0: plain store (+bias[row] optional, row < M_valid guard)
//   MODE 1: fused LSTM cell 1 (Cin = X1 slice added; writes H1st/H12st/h1f/c1)
//   MODE 2: fused LSTM cell 2 (writes H12st h2-slot/h2f/c2)
//   Gate rows are permuted 4*j+{i,f,g,o}, so CTA m-block = 32 hidden units.
// ---------------------------------------------------------------------------
template<int BN, int MODE>
__global__ void __launch_bounds__(256, 1) mma_gemm(
    const __nv_bfloat16* __restrict__ A,
    const __nv_bfloat16* __restrict__ Bm,
    int K3, int M_valid,
    float* __restrict__ C, int ldc,
    const float* __restrict__ Cin, int ldcin,
    const float* __restrict__ bias)
{
    static_assert(MODE == 0 || BN == 64, "gates modes require BN=64");
    constexpr int WARPS_M = (BN == 64) ? 4 : 2;
    constexpr int WARPS_N = 8 / WARPS_M;
    constexpr int WM  = 128 / WARPS_M;   // 32 or 64
    constexpr int MT  = WM / 16;         // 2 or 4
    constexpr int NTL = 4;               // 8-wide n-tiles per warp (WN=32)
    constexpr int A_BUF = 128 * 144;     // 64 bf16 cols padded to 144B rows
    constexpr int B_BUF = BN * 144;
    constexpr int AV = 4;                // 16B vectors per thread per A chunk
    constexpr int BV = BN / 32;

    extern __shared__ __align__(16) char smem[];
    char* sA0 = smem;
    char* sA1 = smem + A_BUF;
    char* sB0 = smem + 2 * A_BUF;
    char* sB1 = smem + 2 * A_BUF + B_BUF;

    const int tid  = threadIdx.x;
    const int wid  = tid >> 5;
    const int lane = tid & 31;
    const int wm = (wid / WARPS_N) * WM;
    const int wn = (wid % WARPS_N) * 32;

    const size_t bm = (size_t)blockIdx.x * 128;
    const size_t bn = (size_t)blockIdx.y * BN;

    const __nv_bfloat16* Ag = A  + bm * (size_t)K3;
    const __nv_bfloat16* Bg = Bm + bn * (size_t)K3;

    const int nst = K3 >> 6;

    float acc[MT][NTL][4];
#pragma unroll
    for (int mt = 0; mt < MT; mt++)
#pragma unroll
        for (int nt = 0; nt < NTL; nt++)
#pragma unroll
            for (int q = 0; q < 4; q++) acc[mt][nt][q] = 0.f;

    // preload chunk 0
    {
#pragma unroll
        for (int v = 0; v < AV; v++) {
            int u = tid + (v << 8); int r = u >> 3, c = u & 7;
            uint4 x = *(const uint4*)(Ag + (size_t)r * K3 + c * 8);
            *(uint4*)(sA0 + r * 144 + c * 16) = x;
        }
#pragma unroll
        for (int v = 0; v < BV; v++) {
            int u = tid + (v << 8); int r = u >> 3, c = u & 7;
            uint4 x = *(const uint4*)(Bg + (size_t)r * K3 + c * 8);
            *(uint4*)(sB0 + r * 144 + c * 16) = x;
        }
    }
    __syncthreads();

    uint4 rA[AV], rB[BV];
    for (int s = 0; s < nst; s++) {
        const bool pf = (s + 1 < nst);
        if (pf) {
            const int k0n = (s + 1) << 6;
#pragma unroll
            for (int v = 0; v < AV; v++) {
                int u = tid + (v << 8); int r = u >> 3, c = u & 7;
                rA[v] = *(const uint4*)(Ag + (size_t)r * K3 + k0n + c * 8);
            }
#pragma unroll
            for (int v = 0; v < BV; v++) {
                int u = tid + (v << 8); int r = u >> 3, c = u & 7;
                rB[v] = *(const uint4*)(Bg + (size_t)r * K3 + k0n + c * 8);
            }
        }
        const char* cA = (s & 1) ? sA1 : sA0;
        const char* cB = (s & 1) ? sB1 : sB0;
#pragma unroll
        for (int kk = 0; kk < 4; kk++) {
            uint32_t af[MT][4], bf[NTL][2];
#pragma unroll
            for (int p = 0; p < 2; p++) {
                int row = wn + p * 16 + (lane & 7) + ((lane >> 4) << 3);
                int kc  = kk * 16 + (((lane >> 3) & 1) << 3);
                ldm_x4(bf[2*p][0], bf[2*p][1], bf[2*p+1][0], bf[2*p+1][1],
                       smem_u32(cB + row * 144 + kc * 2));
            }
#pragma unroll
            for (int mt = 0; mt < MT; mt++) {
                int row = wm + mt * 16 + (lane & 15);
                int kc  = kk * 16 + ((lane >> 4) << 3);
                ldm_x4(af[mt][0], af[mt][1], af[mt][2], af[mt][3],
                       smem_u32(cA + row * 144 + kc * 2));
            }
#pragma unroll
            for (int mt = 0; mt < MT; mt++)
#pragma unroll
                for (int nt = 0; nt < NTL; nt++)
                    mma16816(acc[mt][nt], af[mt], bf[nt]);
        }
        if (pf) {
            char* nA = (s & 1) ? sA0 : sA1;
            char* nB = (s & 1) ? sB0 : sB1;
#pragma unroll
            for (int v = 0; v < AV; v++) {
                int u = tid + (v << 8); int r = u >> 3, c = u & 7;
                *(uint4*)(nA + r * 144 + c * 16) = rA[v];
            }
#pragma unroll
            for (int v = 0; v < BV; v++) {
                int u = tid + (v << 8); int r = u >> 3, c = u & 7;
                *(uint4*)(nB + r * 144 + c * 16) = rB[v];
            }
        }
        __syncthreads();
    }

    if (MODE == 0) {
#pragma unroll
        for (int mt = 0; mt < MT; mt++) {
            int r0 = (int)bm + wm + mt * 16 + (lane >> 2);
#pragma unroll
            for (int nt = 0; nt < NTL; nt++) {
                int c = (int)bn + wn + nt * 8 + (lane & 3) * 2;
                if (r0 < M_valid) {
                    float b0 = bias ? bias[r0] : 0.f;
                    float2 v = { acc[mt][nt][0] + b0, acc[mt][nt][1] + b0 };
                    *(float2*)&C[(size_t)r0 * ldc + c] = v;
                }
                if (r0 + 8 < M_valid) {
                    float b1 = bias ? bias[r0 + 8] : 0.f;
                    float2 v = { acc[mt][nt][2] + b1, acc[mt][nt][3] + b1 };
                    *(float2*)&C[(size_t)(r0 + 8) * ldc + c] = v;
                }
            }
        }
    } else {
        // Stage preactivations (acc + Cin) into transposed smem tile [BN][132].
        float* sg = (float*)smem;
#pragma unroll
        for (int mt = 0; mt < MT; mt++) {
            int r = wm + mt * 16 + (lane >> 2);
#pragma unroll
            for (int nt = 0; nt < NTL; nt++) {
                int cl = wn + nt * 8 + (lane & 3) * 2;
                float v0 = acc[mt][nt][0], v1 = acc[mt][nt][1];
                float v2 = acc[mt][nt][2], v3 = acc[mt][nt][3];
                if (MODE == 1) {
                    const float* cp = Cin + (bm + r) * (size_t)ldcin + bn + cl;
                    v0 += cp[0]; v1 += cp[1];
                    const float* cp8 = cp + (size_t)8 * ldcin;
                    v2 += cp8[0]; v3 += cp8[1];
                }
                sg[cl * 132 + r]           = v0;
                sg[(cl + 1) * 132 + r]     = v1;
                sg[cl * 132 + r + 8]       = v2;
                sg[(cl + 1) * 132 + r + 8] = v3;
            }
        }
        __syncthreads();

        // Cell math: lane = hidden unit (32 per CTA), warp+iter = batch element.
        const int jg = ((int)bm >> 2) + lane;
        const bool jok = (jg < HH);
        const float4 bia = *(const float4*)(bias + bm + 4 * lane);
#pragma unroll
        for (int it = 0; it < 8; it++) {
            int bl = (wid << 3) + it;
            int bg = (int)bn + bl;
            float4 g4 = *(const float4*)&sg[bl * 132 + 4 * lane];
            if (jok) {
                float gi = g4.x + bia.x;
                float gf = g4.y + bia.y;
                float gg = g4.z + bia.z;
                float go = g4.w + bia.w;
                float si = 1.f / (1.f + expf(-gi));
                float sf = 1.f / (1.f + expf(-gf));
                float so = 1.f / (1.f + expf(-go));
                float tg = tanhf(gg);
                float* cst = (MODE == 1) ? g_c1 : g_c2;
                int ci = bg * HH + jg;
                float cn = sf * cst[ci] + si * tg;
                cst[ci] = cn;
                float hn = so * tanhf(cn);
                __nv_bfloat16 hi, lo; split_bf16(hn, hi, lo);
                if (MODE == 1) {
                    size_t o1 = (size_t)bg * K3_H1 + jg;
                    g_H1st[o1]              = hi;
                    g_H1st[o1 + KP_H1]      = lo;
                    g_H1st[o1 + 2 * KP_H1]  = hi;
                    size_t o2 = (size_t)bg * K3_HH + jg;
                    g_H12st[o2]             = hi;
                    g_H12st[o2 + KP_HH]     = lo;
                    g_H12st[o2 + 2 * KP_HH] = hi;
                    g_h1f[ci] = hn;
                } else {
                    size_t o2 = (size_t)bg * K3_HH + 1024 + jg;
                    g_H12st[o2]             = hi;
                    g_H12st[o2 + KP_HH]     = lo;
                    g_H12st[o2 + 2 * KP_HH] = hi;
                    g_h2f[ci] = hn;
                }
            }
        }
    }
}

// ---------------------------------------------------------------------------
// Epilogue helpers
// ---------------------------------------------------------------------------
__global__ void build_z()
{
    int stride = gridDim.x * blockDim.x;
    const int total = BB * K3_HH;
    __nv_bfloat16 z = __float2bfloat16(0.f);
    for (int i = blockIdx.x * blockDim.x + threadIdx.x; i < total; i += stride) {
        int k = i % K3_HH;
        int r = k & (KP_HH - 1);
        g_Zst[i] = (r < 1024) ? g_H12st[i] : z;
    }
}

__global__ void scatter_topic(const int* __restrict__ h)
{
    int idx = blockIdx.x * blockDim.x + threadIdx.x;
    if (idx >= BB * 5) return;
    int b = idx / 5;
    int t = h[idx];
    if (t >= 0 && t < HH) {
        size_t base = (size_t)b * K3_HH + 1024 + t;
        g_Zst[base]             = __float2bfloat16(1.0f);
        g_Zst[base + KP_HH]     = __float2bfloat16(0.0f);
        g_Zst[base + 2 * KP_HH] = __float2bfloat16(1.0f);
    }
}

__global__ void trans_m1()
{
    int stride = gridDim.x * blockDim.x;
    const int total = BB * KP_M1;
    for (int i = blockIdx.x * blockDim.x + threadIdx.x; i < total; i += stride) {
        int b = i / KP_M1, j = i % KP_M1;
        float v = (j < G4) ? g_C1[(size_t)j * BB + b] : 0.f;
        __nv_bfloat16 hi, lo; split_bf16(v, hi, lo);
        size_t base = (size_t)b * K3_M1 + j;
        g_M1st[base]             = hi;
        g_M1st[base + KP_M1]     = lo;
        g_M1st[base + 2 * KP_M1] = hi;
    }
}

__global__ void softmax_dim0(float* __restrict__ out)
{
    __shared__ float red[BB];
    int j = blockIdx.x;          // 0..999
    int b = threadIdx.x;         // 0..255
    float v = g_C2[(size_t)j * BB + b];
    red[b] = v;
    __syncthreads();
    for (int s = 128; s > 0; s >>= 1) {
        if (b < s) red[b] = fmaxf(red[b], red[b + s]);
        __syncthreads();
    }
    float mx = red[0];
    __syncthreads();
    float e = expf(v - mx);
    red[b] = e;
    __syncthreads();
    for (int s = 128; s > 0; s >>= 1) {
        if (b < s) red[b] += red[b + s];
        __syncthreads();
    }
    out[(size_t)b * HH + j] = e / red[0];
}

__global__ void copy_states(float* __restrict__ out)
{
    int idx = blockIdx.x * blockDim.x + threadIdx.x;   // b*1000+j
    if (idx >= BB * HH) return;
    out[256000 + idx]  = g_h1f[idx];
    out[512000 + idx]  = g_c1[idx];
    out[768000 + idx]  = g_h2f[idx];
    out[1024000 + idx] = g_c2[idx];
}

// ---------------------------------------------------------------------------
// Launch (graph-capturable)
// ---------------------------------------------------------------------------
extern "C" void kernel_launch(void* const* d_in, const int* in_sizes, int n_in,
                              void* d_out, int out_size)
{
    const float* input = (const float*)d_in[0];
    const int*   h     = (const int*)  d_in[1];
    const float* W_ih1 = (const float*)d_in[2];
    const float* W_hh1 = (const float*)d_in[3];
    const float* b_ih1 = (const float*)d_in[4];
    const float* b_hh1 = (const float*)d_in[5];
    const float* W_ih2 = (const float*)d_in[6];
    const float* W_hh2 = (const float*)d_in[7];
    const float* b_ih2 = (const float*)d_in[8];
    const float* b_hh2 = (const float*)d_in[9];
    const float* W1    = (const float*)d_in[10];
    const float* b1    = (const float*)d_in[11];
    const float* W2    = (const float*)d_in[12];
    const float* b2    = (const float*)d_in[13];
    float* out = (float*)d_out;

    __nv_bfloat16 *Wxst, *A1st, *Acatst, *W1st, *W2st, *Xst, *H1st, *H12st, *Zst, *M1st;
    float *X1, *C1, *C2, *bias1, *bias2;
    cudaGetSymbolAddress((void**)&Wxst,   g_Wxst);
    cudaGetSymbolAddress((void**)&A1st,   g_A1st);
    cudaGetSymbolAddress((void**)&Acatst, g_Acatst);
    cudaGetSymbolAddress((void**)&W1st,   g_W1st);
    cudaGetSymbolAddress((void**)&W2st,   g_W2st);
    cudaGetSymbolAddress((void**)&Xst,    g_Xst);
    cudaGetSymbolAddress((void**)&H1st,   g_H1st);
    cudaGetSymbolAddress((void**)&H12st,  g_H12st);
    cudaGetSymbolAddress((void**)&Zst,    g_Zst);
    cudaGetSymbolAddress((void**)&M1st,   g_M1st);
    cudaGetSymbolAddress((void**)&X1,     g_X1);
    cudaGetSymbolAddress((void**)&C1,     g_C1);
    cudaGetSymbolAddress((void**)&C2,     g_C2);
    cudaGetSymbolAddress((void**)&bias1,  g_bias1);
    cudaGetSymbolAddress((void**)&bias2,  g_bias2);

    const int SMEM64  = 2 * (128 * 144) + 2 * (64 * 144);    // 55296
    const int SMEM128 = 2 * (128 * 144) + 2 * (128 * 144);   // 73728
    cudaFuncSetAttribute(mma_gemm<128, 0>, cudaFuncAttributeMaxDynamicSharedMemorySize, SMEM128);
    cudaFuncSetAttribute(mma_gemm<64, 0>,  cudaFuncAttributeMaxDynamicSharedMemorySize, SMEM64);
    cudaFuncSetAttribute(mma_gemm<64, 1>,  cudaFuncAttributeMaxDynamicSharedMemorySize, SMEM64);
    cudaFuncSetAttribute(mma_gemm<64, 2>,  cudaFuncAttributeMaxDynamicSharedMemorySize, SMEM64);

    // --- prep ---
    prep_bias<<<16, 256>>>(b_ih1, b_hh1, b_ih2, b_hh2);
    zero_state<<<2048, 256>>>();
    cvt_x<<<8192, 256>>>(input);
    // W_ih1[:, :600] (gate-permuted)
    cvt_weight<<<4096, 256>>>(W_ih1, 1600, nullptr, 0, Wxst, KP_X, 0, KP_X, INS, G4, MP, 1);
    // A1 = W_ih1[:,600:1600] + W_hh1 (gate-permuted)
    cvt_weight<<<4096, 256>>>(W_ih1 + 600, 1600, W_hh1, 1000, A1st, KP_H1, 0, 1024, 1000, G4, MP, 1);
    // Acat halves (gate-permuted)
    cvt_weight<<<4096, 256>>>(W_ih2 + 600, 2600, nullptr, 0, Acatst, KP_HH, 0, 1024, 1000, G4, MP, 1);
    cvt_weight<<<4096, 256>>>(W_ih2 + 1600, 2600, W_hh2, 1000, Acatst, KP_HH, 1024, 1024, 1000, G4, MP, 1);
    // W1 halves (unpermuted)
    cvt_weight<<<4096, 256>>>(W1, 2000, nullptr, 0, W1st, KP_HH, 0, 1024, 1000, G4, MP, 0);
    cvt_weight<<<4096, 256>>>(W1 + 1000, 2000, nullptr, 0, W1st, KP_HH, 1024, 1024, 1000, G4, MP, 0);
    // W2 (unpermuted)
    cvt_weight<<<4096, 256>>>(W2, 4000, nullptr, 0, W2st, KP_M1, 0, KP_M1, G4, 1000, 1024, 0);

    // --- prologue: X1[perm_row, t*256+b] = W_x @ x^T ---
    mma_gemm<128, 0><<<dim3(32, 128), 256, SMEM128>>>(
        Wxst, Xst, K3_X, MP, X1, NX, nullptr, 0, nullptr);

    // --- recurrence (fused gate GEMM + LSTM cell) ---
    for (int t = 0; t < TT; t++) {
        mma_gemm<64, 1><<<dim3(32, 4), 256, SMEM64>>>(
            A1st, H1st, K3_H1, MP, nullptr, 0, X1 + (size_t)t * BB, NX, bias1);
        mma_gemm<64, 2><<<dim3(32, 4), 256, SMEM64>>>(
            Acatst, H12st, K3_HH, MP, nullptr, 0, nullptr, 0, bias2);
    }

    // --- epilogue ---
    build_z<<<6144, 256>>>();
    scatter_topic<<<5, 256>>>(h);
    mma_gemm<64, 0><<<dim3(32, 4), 256, SMEM64>>>(
        W1st, Zst, K3_HH, G4, C1, BB, nullptr, 0, b1);
    trans_m1<<<4096, 256>>>();
    mma_gemm<64, 0><<<dim3(8, 4), 256, SMEM64>>>(
        W2st, M1st, K3_M1, HH, C2, BB, nullptr, 0, b2);
    softmax_dim0<<<1000, 256>>>(out);
    copy_states<<<1000, 256>>>(out);
}

// round 4
// speedup vs baseline: 3.0323x; 1.5113x over previous
#include <cuda_runtime.h>
#include <cuda_bf16.h>
#include <math.h>
#include <stdint.h>

// ---------------------------------------------------------------------------
// Problem constants
// ---------------------------------------------------------------------------
#define BB    256     // batch
#define TT    64      // time steps
#define INS   600     // input size
#define HH    1000    // hidden
#define G4    4000    // 4*hidden
#define MP    4096    // padded gate-row count

// [hi | lo] split layout: K2 = 2 * Kpad. Three MMA passes issued in-kernel:
//   C = Ahi*Bhi + Ahi*Blo + Alo*Bhi   (lo*lo dropped, ~2^-16 relative)
#define KP_X   640
#define K2_X   1280
#define KP_H1  1024
#define K2_H1  2048
#define KP_HH  2048
#define K2_HH  4096
#define KP_M1  4096
#define K2_M1  8192
#define NX     16384   // prologue N = T*B (col n = t*256 + b)

// ---------------------------------------------------------------------------
// Static device scratch
// ---------------------------------------------------------------------------
__device__ __align__(128) __nv_bfloat16 g_Wxst [(size_t)MP * K2_X];   // gate-permuted
__device__ __align__(128) __nv_bfloat16 g_A1st [(size_t)MP * K2_H1];  // gate-permuted
__device__ __align__(128) __nv_bfloat16 g_Acatst[(size_t)MP * K2_HH]; // gate-permuted
__device__ __align__(128) __nv_bfloat16 g_W1st [(size_t)MP * K2_HH];
__device__ __align__(128) __nv_bfloat16 g_W2st [(size_t)1024 * K2_M1];
__device__ __align__(128) __nv_bfloat16 g_Xst  [(size_t)NX * K2_X];
__device__ __align__(128) __nv_bfloat16 g_H1st [BB * K2_H1];
__device__ __align__(128) __nv_bfloat16 g_H12st[BB * K2_HH];
__device__ __align__(128) __nv_bfloat16 g_Zst  [BB * K2_HH];
__device__ __align__(128) __nv_bfloat16 g_M1st [BB * K2_M1];

__device__ __align__(128) float g_X1[(size_t)MP * NX];  // x-part of gates1 (perm rows)
__device__ __align__(128) float g_C1[MP * BB];          // layer1 out [row][b]
__device__ __align__(128) float g_C2[1024 * BB];        // layer2 out [row][b]
__device__ __align__(128) float g_c1[BB * HH];          // cell state [b][j]
__device__ __align__(128) float g_c2[BB * HH];
__device__ __align__(128) float g_h1f[BB * HH];
__device__ __align__(128) float g_h2f[BB * HH];
__device__ __align__(16)  float g_bias1[MP];            // gate-permuted
__device__ __align__(16)  float g_bias2[MP];

// ---------------------------------------------------------------------------
// Helpers
// ---------------------------------------------------------------------------
__device__ __forceinline__ uint32_t smem_u32(const void* p) {
    uint32_t a;
    asm("{ .reg .u64 t; cvta.to.shared.u64 t, %1; cvt.u32.u64 %0, t; }" : "=r"(a) : "l"(p));
    return a;
}

__device__ __forceinline__ void cp16(uint32_t saddr, const void* g) {
    asm volatile("cp.async.cg.shared.global [%0], [%1], 16;" :: "r"(saddr), "l"(g));
}
__device__ __forceinline__ void cp_commit() {
    asm volatile("cp.async.commit_group;" ::: "memory");
}
__device__ __forceinline__ void cp_wait0() {
    asm volatile("cp.async.wait_group 0;" ::: "memory");
}

__device__ __forceinline__ void ldm_x4(uint32_t& r0, uint32_t& r1, uint32_t& r2, uint32_t& r3,
                                       uint32_t addr) {
    asm volatile("ldmatrix.sync.aligned.m8n8.x4.shared.b16 {%0,%1,%2,%3}, [%4];"
        : "=r"(r0), "=r"(r1), "=r"(r2), "=r"(r3) : "r"(addr));
}

__device__ __forceinline__ void mma16816(float* d, const uint32_t* a, const uint32_t* b) {
    asm volatile(
        "mma.sync.aligned.m16n8k16.row.col.f32.bf16.bf16.f32 "
        "{%0,%1,%2,%3}, {%4,%5,%6,%7}, {%8,%9}, {%0,%1,%2,%3};"
        : "+f"(d[0]), "+f"(d[1]), "+f"(d[2]), "+f"(d[3])
        : "r"(a[0]), "r"(a[1]), "r"(a[2]), "r"(a[3]), "r"(b[0]), "r"(b[1]));
}

__device__ __forceinline__ void split_bf16(float v, __nv_bfloat16& hi, __nv_bfloat16& lo) {
    hi = __float2bfloat16(v);
    lo = __float2bfloat16(v - __bfloat162float(hi));
}

// ---------------------------------------------------------------------------
// Weight conversion: fp32 -> [hi(kpad) | lo(kpad)] bf16.
// perm != 0: output row r corresponds to source row (r&3)*1000 + (r>>2).
// ---------------------------------------------------------------------------
__global__ void cvt_weight(const float* __restrict__ src, int src_ld,
                           const float* __restrict__ add, int add_ld,
                           __nv_bfloat16* __restrict__ dst, int kpad,
                           int slot, int cpad, int C, int R, int Rpad, int perm)
{
    int stride = gridDim.x * blockDim.x;
    int total = Rpad * cpad;
    int k2 = 2 * kpad;
    for (int i = blockIdx.x * blockDim.x + threadIdx.x; i < total; i += stride) {
        int r = i / cpad, c = i % cpad;
        int sr; bool ok;
        if (perm) { int j = r >> 2, g = r & 3; sr = g * 1000 + j; ok = (j < 1000); }
        else      { sr = r; ok = (r < R); }
        float v = 0.f;
        if (ok && c < C) {
            v = src[(size_t)sr * src_ld + c];
            if (add) v += add[(size_t)sr * add_ld + c];
        }
        __nv_bfloat16 hi, lo; split_bf16(v, hi, lo);
        size_t base = (size_t)r * k2 + slot + c;
        dst[base]        = hi;
        dst[base + kpad] = lo;
    }
}

// Input x -> [hi | lo]; row n = t*256+b
__global__ void cvt_x(const float* __restrict__ input)
{
    int stride = gridDim.x * blockDim.x;
    const int total = NX * KP_X;
    for (int i = blockIdx.x * blockDim.x + threadIdx.x; i < total; i += stride) {
        int n = i / KP_X, c = i % KP_X;
        int t = n >> 8, b = n & 255;
        float v = (c < INS) ? input[((size_t)b * TT + t) * INS + c] : 0.f;
        __nv_bfloat16 hi, lo; split_bf16(v, hi, lo);
        size_t base = (size_t)n * K2_X + c;
        g_Xst[base]        = hi;
        g_Xst[base + KP_X] = lo;
    }
}

__global__ void prep_bias(const float* b_ih1, const float* b_hh1,
                          const float* b_ih2, const float* b_hh2)
{
    int i = blockIdx.x * blockDim.x + threadIdx.x;
    if (i < MP) {
        int j = i >> 2, g = i & 3;
        int sr = g * 1000 + j;
        float v1 = 0.f, v2 = 0.f;
        if (j < 1000) {
            v1 = b_ih1[sr] + b_hh1[sr];
            v2 = b_ih2[sr] + b_hh2[sr];
        }
        g_bias1[i] = v1;
        g_bias2[i] = v2;
    }
}

__global__ void zero_state()
{
    int stride = gridDim.x * blockDim.x;
    int i0 = blockIdx.x * blockDim.x + threadIdx.x;
    __nv_bfloat16 z = __float2bfloat16(0.f);
    for (int i = i0; i < BB * HH; i += stride) { g_c1[i] = 0.f; g_c2[i] = 0.f; }
    for (int i = i0; i < BB * K2_H1; i += stride) g_H1st[i] = z;
    for (int i = i0; i < BB * K2_HH; i += stride) g_H12st[i] = z;
}

// ---------------------------------------------------------------------------
// 3-pass mma.sync GEMM: C[M,256-chunk] = A[Mpad,K2] @ B[Npad,K2]^T
//   CTA tile 128 x 64, K-chunk 64 real columns (hi+lo both staged), cp.async
//   double buffer, 8 warps (4x2). Three passes per tile pair from smem.
//   MODE 0: plain store (+bias[row], row < M_valid guard)
//   MODE 1: fused LSTM cell 1 (Cin = X1 slice added; writes H1st/H12st/h1f/c1)
//   MODE 2: fused LSTM cell 2 (writes H12st h2-slot/h2f/c2)
// ---------------------------------------------------------------------------
template<int MODE>
__global__ void __launch_bounds__(256, 1) mma_gemm(
    const __nv_bfloat16* __restrict__ A,
    const __nv_bfloat16* __restrict__ Bm,
    int K2, int M_valid,
    float* __restrict__ C, int ldc,
    const float* __restrict__ Cin, int ldcin,
    const float* __restrict__ bias)
{
    constexpr int MT  = 2;               // 2 m-tiles of 16 per warp (WM=32)
    constexpr int NTL = 4;               // 4 n-tiles of 8 per warp (WN=32)
    constexpr int STG_ROWS = 256 + 128;  // Ah(128)+Al(128)+Bh(64)+Bl(64)
    constexpr int STG = STG_ROWS * 144;  // 144B padded rows

    extern __shared__ __align__(16) char smem[];
    const uint32_t sbase = smem_u32(smem);

    const int tid  = threadIdx.x;
    const int wid  = tid >> 5;
    const int lane = tid & 31;
    const int wm = (wid >> 1) * 32;      // 4 warps in M
    const int wn = (wid & 1) * 32;       // 2 warps in N

    const size_t bm = (size_t)blockIdx.x * 128;
    const size_t bn = (size_t)blockIdx.y * 64;

    const __nv_bfloat16* Ag = A  + bm * (size_t)K2;
    const __nv_bfloat16* Bg = Bm + bn * (size_t)K2;
    const int kp  = K2 >> 1;             // Kpad (hi width)
    const int nst = kp >> 6;             // 64-col chunks

    float acc[MT][NTL][4];
#pragma unroll
    for (int mt = 0; mt < MT; mt++)
#pragma unroll
        for (int nt = 0; nt < NTL; nt++)
#pragma unroll
            for (int q = 0; q < 4; q++) acc[mt][nt][q] = 0.f;

    // stage issue: hi+lo chunks of A and B via cp.async
    auto issue = [&](int s) {
        const uint32_t base = sbase + (s & 1) * STG;
        const int k0 = s << 6;
#pragma unroll
        for (int v = 0; v < 4; v++) {
            int u = tid + (v << 8), r = u >> 3, c = u & 7;
            const __nv_bfloat16* ap = Ag + (size_t)r * K2 + k0 + c * 8;
            cp16(base + r * 144 + c * 16, ap);
            cp16(base + (128 + r) * 144 + c * 16, ap + kp);
        }
#pragma unroll
        for (int v = 0; v < 2; v++) {
            int u = tid + (v << 8), r = u >> 3, c = u & 7;
            const __nv_bfloat16* bp = Bg + (size_t)r * K2 + k0 + c * 8;
            cp16(base + (256 + r) * 144 + c * 16, bp);
            cp16(base + (320 + r) * 144 + c * 16, bp + kp);
        }
        cp_commit();
    };

    issue(0);
    for (int s = 0; s < nst; s++) {
        cp_wait0();
        __syncthreads();
        if (s + 1 < nst) issue(s + 1);

        const uint32_t st = sbase + (s & 1) * STG;
#pragma unroll
        for (int kk = 0; kk < 4; kk++) {
            uint32_t bh[NTL][2], bl[NTL][2];
#pragma unroll
            for (int p = 0; p < 2; p++) {
                int row = wn + p * 16 + (lane & 7) + ((lane >> 4) << 3);
                int kc  = kk * 16 + (((lane >> 3) & 1) << 3);
                ldm_x4(bh[2*p][0], bh[2*p][1], bh[2*p+1][0], bh[2*p+1][1],
                       st + (256 + row) * 144 + kc * 2);
                ldm_x4(bl[2*p][0], bl[2*p][1], bl[2*p+1][0], bl[2*p+1][1],
                       st + (320 + row) * 144 + kc * 2);
            }
            uint32_t ah[MT][4], al[MT][4];
#pragma unroll
            for (int mt = 0; mt < MT; mt++) {
                int row = wm + mt * 16 + (lane & 15);
                int kc  = kk * 16 + ((lane >> 4) << 3);
                ldm_x4(ah[mt][0], ah[mt][1], ah[mt][2], ah[mt][3],
                       st + row * 144 + kc * 2);
                ldm_x4(al[mt][0], al[mt][1], al[mt][2], al[mt][3],
                       st + (128 + row) * 144 + kc * 2);
            }
#pragma unroll
            for (int mt = 0; mt < MT; mt++)
#pragma unroll
                for (int nt = 0; nt < NTL; nt++) {
                    mma16816(acc[mt][nt], ah[mt], bh[nt]);   // hi*hi
                    mma16816(acc[mt][nt], ah[mt], bl[nt]);   // hi*lo
                    mma16816(acc[mt][nt], al[mt], bh[nt]);   // lo*hi
                }
        }
        __syncthreads();
    }

    if (MODE == 0) {
#pragma unroll
        for (int mt = 0; mt < MT; mt++) {
            int r0 = (int)bm + wm + mt * 16 + (lane >> 2);
#pragma unroll
            for (int nt = 0; nt < NTL; nt++) {
                int c = (int)bn + wn + nt * 8 + (lane & 3) * 2;
                if (r0 < M_valid) {
                    float b0 = bias ? bias[r0] : 0.f;
                    float2 v = { acc[mt][nt][0] + b0, acc[mt][nt][1] + b0 };
                    *(float2*)&C[(size_t)r0 * ldc + c] = v;
                }
                if (r0 + 8 < M_valid) {
                    float b1 = bias ? bias[r0 + 8] : 0.f;
                    float2 v = { acc[mt][nt][2] + b1, acc[mt][nt][3] + b1 };
                    *(float2*)&C[(size_t)(r0 + 8) * ldc + c] = v;
                }
            }
        }
    } else {
        // Stage preactivations (acc + Cin) into transposed smem tile [64][132].
        float* sg = (float*)smem;
#pragma unroll
        for (int mt = 0; mt < MT; mt++) {
            int r = wm + mt * 16 + (lane >> 2);
#pragma unroll
            for (int nt = 0; nt < NTL; nt++) {
                int cl = wn + nt * 8 + (lane & 3) * 2;
                float v0 = acc[mt][nt][0], v1 = acc[mt][nt][1];
                float v2 = acc[mt][nt][2], v3 = acc[mt][nt][3];
                if (MODE == 1) {
                    const float* cp = Cin + (bm + r) * (size_t)ldcin + bn + cl;
                    v0 += cp[0]; v1 += cp[1];
                    const float* cp8 = cp + (size_t)8 * ldcin;
                    v2 += cp8[0]; v3 += cp8[1];
                }
                sg[cl * 132 + r]           = v0;
                sg[(cl + 1) * 132 + r]     = v1;
                sg[cl * 132 + r + 8]       = v2;
                sg[(cl + 1) * 132 + r + 8] = v3;
            }
        }
        __syncthreads();

        // Cell math: lane = hidden unit (32 per CTA), warp+iter = batch element.
        const int jg = ((int)bm >> 2) + lane;
        const bool jok = (jg < HH);
        const float4 bia = *(const float4*)(bias + bm + 4 * lane);
#pragma unroll
        for (int it = 0; it < 8; it++) {
            int bl2 = (wid << 3) + it;
            int bg = (int)bn + bl2;
            float4 g4 = *(const float4*)&sg[bl2 * 132 + 4 * lane];
            if (jok) {
                float gi = g4.x + bia.x;
                float gf = g4.y + bia.y;
                float gg = g4.z + bia.z;
                float go = g4.w + bia.w;
                float si = 1.f / (1.f + expf(-gi));
                float sf = 1.f / (1.f + expf(-gf));
                float so = 1.f / (1.f + expf(-go));
                float tg = tanhf(gg);
                float* cst = (MODE == 1) ? g_c1 : g_c2;
                int ci = bg * HH + jg;
                float cn = sf * cst[ci] + si * tg;
                cst[ci] = cn;
                float hn = so * tanhf(cn);
                __nv_bfloat16 hi, lo; split_bf16(hn, hi, lo);
                if (MODE == 1) {
                    size_t o1 = (size_t)bg * K2_H1 + jg;
                    g_H1st[o1]          = hi;
                    g_H1st[o1 + KP_H1]  = lo;
                    size_t o2 = (size_t)bg * K2_HH + jg;
                    g_H12st[o2]         = hi;
                    g_H12st[o2 + KP_HH] = lo;
                    g_h1f[ci] = hn;
                } else {
                    size_t o2 = (size_t)bg * K2_HH + 1024 + jg;
                    g_H12st[o2]         = hi;
                    g_H12st[o2 + KP_HH] = lo;
                    g_h2f[ci] = hn;
                }
            }
        }
    }
}

// ---------------------------------------------------------------------------
// Epilogue helpers
// ---------------------------------------------------------------------------
__global__ void build_z()
{
    int stride = gridDim.x * blockDim.x;
    const int total = BB * K2_HH;
    __nv_bfloat16 z = __float2bfloat16(0.f);
    for (int i = blockIdx.x * blockDim.x + threadIdx.x; i < total; i += stride) {
        int k = i % K2_HH;
        int r = k & (KP_HH - 1);          // position within hi or lo half
        g_Zst[i] = (r < 1024) ? g_H12st[i] : z;   // h1 slots copied, topic zeroed
    }
}

__global__ void scatter_topic(const int* __restrict__ h)
{
    int idx = blockIdx.x * blockDim.x + threadIdx.x;
    if (idx >= BB * 5) return;
    int b = idx / 5;
    int t = h[idx];
    if (t >= 0 && t < HH) {
        size_t base = (size_t)b * K2_HH + 1024 + t;
        g_Zst[base]         = __float2bfloat16(1.0f);   // hi slot
        g_Zst[base + KP_HH] = __float2bfloat16(0.0f);   // lo slot
    }
}

__global__ void trans_m1()
{
    int stride = gridDim.x * blockDim.x;
    const int total = BB * KP_M1;
    for (int i = blockIdx.x * blockDim.x + threadIdx.x; i < total; i += stride) {
        int b = i / KP_M1, j = i % KP_M1;
        float v = (j < G4) ? g_C1[(size_t)j * BB + b] : 0.f;
        __nv_bfloat16 hi, lo; split_bf16(v, hi, lo);
        size_t base = (size_t)b * K2_M1 + j;
        g_M1st[base]         = hi;
        g_M1st[base + KP_M1] = lo;
    }
}

__global__ void softmax_dim0(float* __restrict__ out)
{
    __shared__ float red[BB];
    int j = blockIdx.x;          // 0..999
    int b = threadIdx.x;         // 0..255
    float v = g_C2[(size_t)j * BB + b];
    red[b] = v;
    __syncthreads();
    for (int s = 128; s > 0; s >>= 1) {
        if (b < s) red[b] = fmaxf(red[b], red[b + s]);
        __syncthreads();
    }
    float mx = red[0];
    __syncthreads();
    float e = expf(v - mx);
    red[b] = e;
    __syncthreads();
    for (int s = 128; s > 0; s >>= 1) {
        if (b < s) red[b] += red[b + s];
        __syncthreads();
    }
    out[(size_t)b * HH + j] = e / red[0];
}

__global__ void copy_states(float* __restrict__ out)
{
    int idx = blockIdx.x * blockDim.x + threadIdx.x;
    if (idx >= BB * HH) return;
    out[256000 + idx]  = g_h1f[idx];
    out[512000 + idx]  = g_c1[idx];
    out[768000 + idx]  = g_h2f[idx];
    out[1024000 + idx] = g_c2[idx];
}

// ---------------------------------------------------------------------------
// Launch (graph-capturable)
// ---------------------------------------------------------------------------
extern "C" void kernel_launch(void* const* d_in, const int* in_sizes, int n_in,
                              void* d_out, int out_size)
{
    const float* input = (const float*)d_in[0];
    const int*   h     = (const int*)  d_in[1];
    const float* W_ih1 = (const float*)d_in[2];
    const float* W_hh1 = (const float*)d_in[3];
    const float* b_ih1 = (const float*)d_in[4];
    const float* b_hh1 = (const float*)d_in[5];
    const float* W_ih2 = (const float*)d_in[6];
    const float* W_hh2 = (const float*)d_in[7];
    const float* b_ih2 = (const float*)d_in[8];
    const float* b_hh2 = (const float*)d_in[9];
    const float* W1    = (const float*)d_in[10];
    const float* b1    = (const float*)d_in[11];
    const float* W2    = (const float*)d_in[12];
    const float* b2    = (const float*)d_in[13];
    float* out = (float*)d_out;

    __nv_bfloat16 *Wxst, *A1st, *Acatst, *W1st, *W2st, *Xst, *H1st, *H12st, *Zst, *M1st;
    float *X1, *C1, *C2, *bias1, *bias2;
    cudaGetSymbolAddress((void**)&Wxst,   g_Wxst);
    cudaGetSymbolAddress((void**)&A1st,   g_A1st);
    cudaGetSymbolAddress((void**)&Acatst, g_Acatst);
    cudaGetSymbolAddress((void**)&W1st,   g_W1st);
    cudaGetSymbolAddress((void**)&W2st,   g_W2st);
    cudaGetSymbolAddress((void**)&Xst,    g_Xst);
    cudaGetSymbolAddress((void**)&H1st,   g_H1st);
    cudaGetSymbolAddress((void**)&H12st,  g_H12st);
    cudaGetSymbolAddress((void**)&Zst,    g_Zst);
    cudaGetSymbolAddress((void**)&M1st,   g_M1st);
    cudaGetSymbolAddress((void**)&X1,     g_X1);
    cudaGetSymbolAddress((void**)&C1,     g_C1);
    cudaGetSymbolAddress((void**)&C2,     g_C2);
    cudaGetSymbolAddress((void**)&bias1,  g_bias1);
    cudaGetSymbolAddress((void**)&bias2,  g_bias2);

    const int SMEM = 2 * ((256 + 128) * 144);   // 110,592 B
    cudaFuncSetAttribute(mma_gemm<0>, cudaFuncAttributeMaxDynamicSharedMemorySize, SMEM);
    cudaFuncSetAttribute(mma_gemm<1>, cudaFuncAttributeMaxDynamicSharedMemorySize, SMEM);
    cudaFuncSetAttribute(mma_gemm<2>, cudaFuncAttributeMaxDynamicSharedMemorySize, SMEM);

    // --- prep ---
    prep_bias<<<16, 256>>>(b_ih1, b_hh1, b_ih2, b_hh2);
    zero_state<<<2048, 256>>>();
    cvt_x<<<8192, 256>>>(input);
    cvt_weight<<<4096, 256>>>(W_ih1, 1600, nullptr, 0, Wxst, KP_X, 0, KP_X, INS, G4, MP, 1);
    cvt_weight<<<4096, 256>>>(W_ih1 + 600, 1600, W_hh1, 1000, A1st, KP_H1, 0, 1024, 1000, G4, MP, 1);
    cvt_weight<<<4096, 256>>>(W_ih2 + 600, 2600, nullptr, 0, Acatst, KP_HH, 0, 1024, 1000, G4, MP, 1);
    cvt_weight<<<4096, 256>>>(W_ih2 + 1600, 2600, W_hh2, 1000, Acatst, KP_HH, 1024, 1024, 1000, G4, MP, 1);
    cvt_weight<<<4096, 256>>>(W1, 2000, nullptr, 0, W1st, KP_HH, 0, 1024, 1000, G4, MP, 0);
    cvt_weight<<<4096, 256>>>(W1 + 1000, 2000, nullptr, 0, W1st, KP_HH, 1024, 1024, 1000, G4, MP, 0);
    cvt_weight<<<4096, 256>>>(W2, 4000, nullptr, 0, W2st, KP_M1, 0, KP_M1, G4, 1000, 1024, 0);

    // --- prologue: X1[perm_row, t*256+b] = W_x @ x^T ---
    mma_gemm<0><<<dim3(32, 256), 256, SMEM>>>(
        Wxst, Xst, K2_X, MP, X1, NX, nullptr, 0, nullptr);

    // --- recurrence (fused gate GEMM + LSTM cell) ---
    for (int t = 0; t < TT; t++) {
        mma_gemm<1><<<dim3(32, 4), 256, SMEM>>>(
            A1st, H1st, K2_H1, MP, nullptr, 0, X1 + (size_t)t * BB, NX, bias1);
        mma_gemm<2><<<dim3(32, 4), 256, SMEM>>>(
            Acatst, H12st, K2_HH, MP, nullptr, 0, nullptr, 0, bias2);
    }

    // --- epilogue ---
    build_z<<<6144, 256>>>();
    scatter_topic<<<5, 256>>>(h);
    mma_gemm<0><<<dim3(32, 4), 256, SMEM>>>(
        W1st, Zst, K2_HH, G4, C1, BB, nullptr, 0, b1);
    trans_m1<<<4096, 256>>>();
    mma_gemm<0><<<dim3(8, 4), 256, SMEM>>>(
        W2st, M1st, K2_M1, HH, C2, BB, nullptr, 0, b2);
    softmax_dim0<<<1000, 256>>>(out);
    copy_states<<<1000, 256>>>(out);
}

// round 5
// speedup vs baseline: 3.0696x; 1.0123x over previous
#include <cuda_runtime.h>
#include <cuda_bf16.h>
#include <math.h>
#include <stdint.h>

// ---------------------------------------------------------------------------
// Problem constants
// ---------------------------------------------------------------------------
#define BB    256     // batch
#define TT    64      // time steps
#define INS   600     // input size
#define HH    1000    // hidden
#define G4    4000    // 4*hidden
#define MP    4096    // padded gate-row count

// [hi | lo] split layout: K2 = 2 * Kpad. Three MMA passes issued in-kernel:
//   C = Ahi*Bhi + Ahi*Blo + Alo*Bhi   (lo*lo dropped, ~2^-16 relative)
#define KP_X   640
#define K2_X   1280
#define KP_H1  1024
#define K2_H1  2048
#define KP_HH  2048
#define K2_HH  4096
#define KP_M1  4096
#define K2_M1  8192
#define NX     16384   // prologue N = T*B (col n = t*256 + b)

#define NCTA   128     // persistent kernel CTAs (1 per SM, 148 available)

// ---------------------------------------------------------------------------
// Static device scratch
// ---------------------------------------------------------------------------
__device__ __align__(128) __nv_bfloat16 g_Wxst [(size_t)MP * K2_X];   // gate-permuted
__device__ __align__(128) __nv_bfloat16 g_A1st [(size_t)MP * K2_H1];  // gate-permuted
__device__ __align__(128) __nv_bfloat16 g_Acatst[(size_t)MP * K2_HH]; // gate-permuted
__device__ __align__(128) __nv_bfloat16 g_W1st [(size_t)MP * K2_HH];
__device__ __align__(128) __nv_bfloat16 g_W2st [(size_t)1024 * K2_M1];
__device__ __align__(128) __nv_bfloat16 g_Xst  [(size_t)NX * K2_X];
__device__ __align__(128) __nv_bfloat16 g_H1d [2][BB * K2_H1];        // double-buffered
__device__ __align__(128) __nv_bfloat16 g_H12d[2][BB * K2_HH];        // double-buffered
__device__ __align__(128) __nv_bfloat16 g_Zst  [BB * K2_HH];
__device__ __align__(128) __nv_bfloat16 g_M1st [BB * K2_M1];

__device__ __align__(128) float g_X1[(size_t)MP * NX];  // x-part of gates1 (perm rows)
__device__ __align__(128) float g_C1[MP * BB];          // layer1 out [row][b]
__device__ __align__(128) float g_C2[1024 * BB];        // layer2 out [row][b]
__device__ __align__(128) float g_c1[BB * HH];          // cell state [b][j]
__device__ __align__(128) float g_c2[BB * HH];
__device__ __align__(128) float g_h1f[BB * HH];
__device__ __align__(128) float g_h2f[BB * HH];
__device__ __align__(16)  float g_bias1[MP];            // gate-permuted
__device__ __align__(16)  float g_bias2[MP];

// grid barrier state
__device__ unsigned g_bar_count;
__device__ unsigned g_bar_phase;

__global__ void init_bar() { g_bar_count = 0; g_bar_phase = 0; }

// ---------------------------------------------------------------------------
// Helpers
// ---------------------------------------------------------------------------
__device__ __forceinline__ uint32_t smem_u32(const void* p) {
    uint32_t a;
    asm("{ .reg .u64 t; cvta.to.shared.u64 t, %1; cvt.u32.u64 %0, t; }" : "=r"(a) : "l"(p));
    return a;
}

__device__ __forceinline__ void cp16(uint32_t saddr, const void* g) {
    asm volatile("cp.async.cg.shared.global [%0], [%1], 16;" :: "r"(saddr), "l"(g));
}
__device__ __forceinline__ void cp_commit() {
    asm volatile("cp.async.commit_group;" ::: "memory");
}
__device__ __forceinline__ void cp_wait0() {
    asm volatile("cp.async.wait_group 0;" ::: "memory");
}

__device__ __forceinline__ void ldm_x4(uint32_t& r0, uint32_t& r1, uint32_t& r2, uint32_t& r3,
                                       uint32_t addr) {
    asm volatile("ldmatrix.sync.aligned.m8n8.x4.shared.b16 {%0,%1,%2,%3}, [%4];"
        : "=r"(r0), "=r"(r1), "=r"(r2), "=r"(r3) : "r"(addr));
}

__device__ __forceinline__ void mma16816(float* d, const uint32_t* a, const uint32_t* b) {
    asm volatile(
        "mma.sync.aligned.m16n8k16.row.col.f32.bf16.bf16.f32 "
        "{%0,%1,%2,%3}, {%4,%5,%6,%7}, {%8,%9}, {%0,%1,%2,%3};"
        : "+f"(d[0]), "+f"(d[1]), "+f"(d[2]), "+f"(d[3])
        : "r"(a[0]), "r"(a[1]), "r"(a[2]), "r"(a[3]), "r"(b[0]), "r"(b[1]));
}

__device__ __forceinline__ void split_bf16(float v, __nv_bfloat16& hi, __nv_bfloat16& lo) {
    hi = __float2bfloat16(v);
    lo = __float2bfloat16(v - __bfloat162float(hi));
}

// Grid-wide barrier: wait until g_bar_phase >= target. All NCTA CTAs must be
// co-resident (guaranteed: 128 CTAs, 1/SM on a 148-SM chip).
__device__ __forceinline__ void grid_barrier(unsigned target)
{
    __syncthreads();
    if (threadIdx.x == 0) {
        __threadfence();
        unsigned prev = atomicAdd(&g_bar_count, 1);
        if (prev == NCTA - 1) {
            g_bar_count = 0;
            __threadfence();
            atomicAdd(&g_bar_phase, 1);
        } else {
            unsigned p;
            do {
                asm volatile("ld.acquire.gpu.u32 %0, [%1];" : "=r"(p) : "l"(&g_bar_phase));
                if (p < target) __nanosleep(64);
            } while (p < target);
        }
        __threadfence();
    }
    __syncthreads();
}

// ---------------------------------------------------------------------------
// Weight conversion: fp32 -> [hi(kpad) | lo(kpad)] bf16.
// perm != 0: output row r corresponds to source row (r&3)*1000 + (r>>2).
// ---------------------------------------------------------------------------
__global__ void cvt_weight(const float* __restrict__ src, int src_ld,
                           const float* __restrict__ add, int add_ld,
                           __nv_bfloat16* __restrict__ dst, int kpad,
                           int slot, int cpad, int C, int R, int Rpad, int perm)
{
    int stride = gridDim.x * blockDim.x;
    int total = Rpad * cpad;
    int k2 = 2 * kpad;
    for (int i = blockIdx.x * blockDim.x + threadIdx.x; i < total; i += stride) {
        int r = i / cpad, c = i % cpad;
        int sr; bool ok;
        if (perm) { int j = r >> 2, g = r & 3; sr = g * 1000 + j; ok = (j < 1000); }
        else      { sr = r; ok = (r < R); }
        float v = 0.f;
        if (ok && c < C) {
            v = src[(size_t)sr * src_ld + c];
            if (add) v += add[(size_t)sr * add_ld + c];
        }
        __nv_bfloat16 hi, lo; split_bf16(v, hi, lo);
        size_t base = (size_t)r * k2 + slot + c;
        dst[base]        = hi;
        dst[base + kpad] = lo;
    }
}

// Input x -> [hi | lo]; row n = t*256+b
__global__ void cvt_x(const float* __restrict__ input)
{
    int stride = gridDim.x * blockDim.x;
    const int total = NX * KP_X;
    for (int i = blockIdx.x * blockDim.x + threadIdx.x; i < total; i += stride) {
        int n = i / KP_X, c = i % KP_X;
        int t = n >> 8, b = n & 255;
        float v = (c < INS) ? input[((size_t)b * TT + t) * INS + c] : 0.f;
        __nv_bfloat16 hi, lo; split_bf16(v, hi, lo);
        size_t base = (size_t)n * K2_X + c;
        g_Xst[base]        = hi;
        g_Xst[base + KP_X] = lo;
    }
}

__global__ void prep_bias(const float* b_ih1, const float* b_hh1,
                          const float* b_ih2, const float* b_hh2)
{
    int i = blockIdx.x * blockDim.x + threadIdx.x;
    if (i < MP) {
        int j = i >> 2, g = i & 3;
        int sr = g * 1000 + j;
        float v1 = 0.f, v2 = 0.f;
        if (j < 1000) {
            v1 = b_ih1[sr] + b_hh1[sr];
            v2 = b_ih2[sr] + b_hh2[sr];
        }
        g_bias1[i] = v1;
        g_bias2[i] = v2;
    }
}

__global__ void zero_state()
{
    int stride = gridDim.x * blockDim.x;
    int i0 = blockIdx.x * blockDim.x + threadIdx.x;
    __nv_bfloat16 z = __float2bfloat16(0.f);
    for (int i = i0; i < BB * HH; i += stride) { g_c1[i] = 0.f; g_c2[i] = 0.f; }
    __nv_bfloat16* h1 = &g_H1d[0][0];
    for (int i = i0; i < 2 * BB * K2_H1; i += stride) h1[i] = z;
    __nv_bfloat16* h12 = &g_H12d[0][0];
    for (int i = i0; i < 2 * BB * K2_HH; i += stride) h12[i] = z;
}

// ---------------------------------------------------------------------------
// 3-pass mma.sync GEMM tile: C[bm:bm+128, bn:bn+64] = A @ B^T
//   K-chunk 64 real columns (hi+lo both staged), cp.async double buffer,
//   8 warps (4x2). Three passes per tile pair from smem.
//   MODE 0: plain store (+bias[row], row < M_valid guard)
//   MODE 1: fused LSTM cell 1 (Cin = X1 slice added; writes Hw1/Hw12/hf/cst)
//   MODE 2: fused LSTM cell 2 (writes Hw12 h2-slot/hf/cst)
// ---------------------------------------------------------------------------
template<int MODE>
__device__ __forceinline__ void gemm_tile(
    const __nv_bfloat16* __restrict__ A,
    const __nv_bfloat16* __restrict__ Bm,
    int K2, int M_valid,
    float* __restrict__ C, int ldc,
    const float* __restrict__ Cin, int ldcin,
    const float* __restrict__ bias,
    int bm, int bn,
    float* __restrict__ cst,
    __nv_bfloat16* __restrict__ Hw1,
    __nv_bfloat16* __restrict__ Hw12,
    float* __restrict__ hf,
    char* smem)
{
    constexpr int MT  = 2;               // 2 m-tiles of 16 per warp (WM=32)
    constexpr int NTL = 4;               // 4 n-tiles of 8 per warp (WN=32)
    constexpr int STG = (256 + 128) * 144;  // Ah(128)+Al(128)+Bh(64)+Bl(64), 144B rows

    const uint32_t sbase = smem_u32(smem);
    const int tid  = threadIdx.x;
    const int wid  = tid >> 5;
    const int lane = tid & 31;
    const int wm = (wid >> 1) * 32;      // 4 warps in M
    const int wn = (wid & 1) * 32;       // 2 warps in N

    const __nv_bfloat16* Ag = A  + (size_t)bm * K2;
    const __nv_bfloat16* Bg = Bm + (size_t)bn * K2;
    const int kp  = K2 >> 1;             // Kpad (hi width)
    const int nst = kp >> 6;             // 64-col chunks

    float acc[MT][NTL][4];
#pragma unroll
    for (int mt = 0; mt < MT; mt++)
#pragma unroll
        for (int nt = 0; nt < NTL; nt++)
#pragma unroll
            for (int q = 0; q < 4; q++) acc[mt][nt][q] = 0.f;

    auto issue = [&](int s) {
        const uint32_t base = sbase + (s & 1) * STG;
        const int k0 = s << 6;
#pragma unroll
        for (int v = 0; v < 4; v++) {
            int u = tid + (v << 8), r = u >> 3, c = u & 7;
            const __nv_bfloat16* ap = Ag + (size_t)r * K2 + k0 + c * 8;
            cp16(base + r * 144 + c * 16, ap);
            cp16(base + (128 + r) * 144 + c * 16, ap + kp);
        }
#pragma unroll
        for (int v = 0; v < 2; v++) {
            int u = tid + (v << 8), r = u >> 3, c = u & 7;
            const __nv_bfloat16* bp = Bg + (size_t)r * K2 + k0 + c * 8;
            cp16(base + (256 + r) * 144 + c * 16, bp);
            cp16(base + (320 + r) * 144 + c * 16, bp + kp);
        }
        cp_commit();
    };

    issue(0);
    for (int s = 0; s < nst; s++) {
        cp_wait0();
        __syncthreads();
        if (s + 1 < nst) issue(s + 1);

        const uint32_t st = sbase + (s & 1) * STG;
#pragma unroll
        for (int kk = 0; kk < 4; kk++) {
            uint32_t bh[NTL][2], bl[NTL][2];
#pragma unroll
            for (int p = 0; p < 2; p++) {
                int row = wn + p * 16 + (lane & 7) + ((lane >> 4) << 3);
                int kc  = kk * 16 + (((lane >> 3) & 1) << 3);
                ldm_x4(bh[2*p][0], bh[2*p][1], bh[2*p+1][0], bh[2*p+1][1],
                       st + (256 + row) * 144 + kc * 2);
                ldm_x4(bl[2*p][0], bl[2*p][1], bl[2*p+1][0], bl[2*p+1][1],
                       st + (320 + row) * 144 + kc * 2);
            }
            uint32_t ah[MT][4], al[MT][4];
#pragma unroll
            for (int mt = 0; mt < MT; mt++) {
                int row = wm + mt * 16 + (lane & 15);
                int kc  = kk * 16 + ((lane >> 4) << 3);
                ldm_x4(ah[mt][0], ah[mt][1], ah[mt][2], ah[mt][3],
                       st + row * 144 + kc * 2);
                ldm_x4(al[mt][0], al[mt][1], al[mt][2], al[mt][3],
                       st + (128 + row) * 144 + kc * 2);
            }
#pragma unroll
            for (int mt = 0; mt < MT; mt++)
#pragma unroll
                for (int nt = 0; nt < NTL; nt++) {
                    mma16816(acc[mt][nt], ah[mt], bh[nt]);   // hi*hi
                    mma16816(acc[mt][nt], ah[mt], bl[nt]);   // hi*lo
                    mma16816(acc[mt][nt], al[mt], bh[nt]);   // lo*hi
                }
        }
        __syncthreads();
    }

    if (MODE == 0) {
#pragma unroll
        for (int mt = 0; mt < MT; mt++) {
            int r0 = bm + wm + mt * 16 + (lane >> 2);
#pragma unroll
            for (int nt = 0; nt < NTL; nt++) {
                int c = bn + wn + nt * 8 + (lane & 3) * 2;
                if (r0 < M_valid) {
                    float b0 = bias ? bias[r0] : 0.f;
                    float2 v = { acc[mt][nt][0] + b0, acc[mt][nt][1] + b0 };
                    *(float2*)&C[(size_t)r0 * ldc + c] = v;
                }
                if (r0 + 8 < M_valid) {
                    float b1 = bias ? bias[r0 + 8] : 0.f;
                    float2 v = { acc[mt][nt][2] + b1, acc[mt][nt][3] + b1 };
                    *(float2*)&C[(size_t)(r0 + 8) * ldc + c] = v;
                }
            }
        }
    } else {
        // Stage preactivations (acc + Cin) into transposed smem tile [64][132].
        float* sg = (float*)smem;
#pragma unroll
        for (int mt = 0; mt < MT; mt++) {
            int r = wm + mt * 16 + (lane >> 2);
#pragma unroll
            for (int nt = 0; nt < NTL; nt++) {
                int cl = wn + nt * 8 + (lane & 3) * 2;
                float v0 = acc[mt][nt][0], v1 = acc[mt][nt][1];
                float v2 = acc[mt][nt][2], v3 = acc[mt][nt][3];
                if (MODE == 1) {
                    const float* cp = Cin + (size_t)(bm + r) * ldcin + bn + cl;
                    v0 += cp[0]; v1 += cp[1];
                    const float* cp8 = cp + (size_t)8 * ldcin;
                    v2 += cp8[0]; v3 += cp8[1];
                }
                sg[cl * 132 + r]           = v0;
                sg[(cl + 1) * 132 + r]     = v1;
                sg[cl * 132 + r + 8]       = v2;
                sg[(cl + 1) * 132 + r + 8] = v3;
            }
        }
        __syncthreads();

        // Cell math: lane = hidden unit (32 per CTA), warp+iter = batch element.
        const int jg = (bm >> 2) + lane;
        const bool jok = (jg < HH);
        const float4 bia = *(const float4*)(bias + bm + 4 * lane);
#pragma unroll
        for (int it = 0; it < 8; it++) {
            int bl2 = (wid << 3) + it;
            int bg = bn + bl2;
            float4 g4 = *(const float4*)&sg[bl2 * 132 + 4 * lane];
            if (jok) {
                float gi = g4.x + bia.x;
                float gf = g4.y + bia.y;
                float gg = g4.z + bia.z;
                float go = g4.w + bia.w;
                float si = 1.f / (1.f + expf(-gi));
                float sf = 1.f / (1.f + expf(-gf));
                float so = 1.f / (1.f + expf(-go));
                float tg = tanhf(gg);
                int ci = bg * HH + jg;
                float cn = sf * cst[ci] + si * tg;
                cst[ci] = cn;
                float hn = so * tanhf(cn);
                __nv_bfloat16 hi, lo; split_bf16(hn, hi, lo);
                if (MODE == 1) {
                    size_t o1 = (size_t)bg * K2_H1 + jg;
                    Hw1[o1]          = hi;
                    Hw1[o1 + KP_H1]  = lo;
                    size_t o2 = (size_t)bg * K2_HH + jg;
                    Hw12[o2]         = hi;
                    Hw12[o2 + KP_HH] = lo;
                    hf[ci] = hn;
                } else {
                    size_t o2 = (size_t)bg * K2_HH + 1024 + jg;
                    Hw12[o2]         = hi;
                    Hw12[o2 + KP_HH] = lo;
                    hf[ci] = hn;
                }
            }
        }
    }
    __syncthreads();
}

// Global wrapper (MODE 0 only: prologue + epilogue GEMMs)
template<int MODE>
__global__ void __launch_bounds__(256, 1) mma_gemm(
    const __nv_bfloat16* __restrict__ A,
    const __nv_bfloat16* __restrict__ Bm,
    int K2, int M_valid,
    float* __restrict__ C, int ldc,
    const float* __restrict__ bias)
{
    extern __shared__ __align__(16) char smem[];
    gemm_tile<MODE>(A, Bm, K2, M_valid, C, ldc, nullptr, 0, bias,
                    blockIdx.x * 128, blockIdx.y * 64,
                    nullptr, nullptr, nullptr, nullptr, smem);
}

// ---------------------------------------------------------------------------
// Persistent recurrence kernel: 65 phases, 1 grid barrier each.
// Phase i: [i<64] gates1(i) = X1(i) + A1*h1(i-1) -> cell1 -> h1(i)
//          [i>=1] gates2(i-1) = Acat*[h1(i-1); h2(i-2)] -> cell2 -> h2(i-1)
// Both read buffer (i&1); cells write buffer ((i+1)&1). c1/c2 are CTA-private.
// ---------------------------------------------------------------------------
__global__ void __launch_bounds__(256, 1) lstm_persist()
{
    extern __shared__ __align__(16) char smem[];
    const int c  = blockIdx.x;
    const int bm = (c >> 2) * 128;
    const int bn = (c & 3) * 64;

    for (int i = 0; i <= TT; i++) {
        const __nv_bfloat16* H1r  = g_H1d [i & 1];
        const __nv_bfloat16* H12r = g_H12d[i & 1];
        __nv_bfloat16* H1w  = g_H1d [(i + 1) & 1];
        __nv_bfloat16* H12w = g_H12d[(i + 1) & 1];

        if (i < TT)
            gemm_tile<1>(g_A1st, H1r, K2_H1, MP, nullptr, 0,
                         g_X1 + (size_t)i * BB, NX, g_bias1,
                         bm, bn, g_c1, H1w, H12w, g_h1f, smem);
        if (i >= 1)
            gemm_tile<2>(g_Acatst, H12r, K2_HH, MP, nullptr, 0,
                         nullptr, 0, g_bias2,
                         bm, bn, g_c2, nullptr, H12w, g_h2f, smem);

        if (i < TT) grid_barrier(i + 1);
    }
}

// ---------------------------------------------------------------------------
// Epilogue helpers
// ---------------------------------------------------------------------------
__global__ void build_z()
{
    int stride = gridDim.x * blockDim.x;
    const int total = BB * KP_HH;
    for (int i = blockIdx.x * blockDim.x + threadIdx.x; i < total; i += stride) {
        int b = i / KP_HH, k = i % KP_HH;
        float v = (k < HH) ? g_h1f[b * HH + k] : 0.f;   // topic half (k>=1024) zero
        if (k >= 1024) v = 0.f;
        __nv_bfloat16 hi, lo; split_bf16(v, hi, lo);
        size_t base = (size_t)b * K2_HH + k;
        g_Zst[base]         = hi;
        g_Zst[base + KP_HH] = lo;
    }
}

__global__ void scatter_topic(const int* __restrict__ h)
{
    int idx = blockIdx.x * blockDim.x + threadIdx.x;
    if (idx >= BB * 5) return;
    int b = idx / 5;
    int t = h[idx];
    if (t >= 0 && t < HH) {
        size_t base = (size_t)b * K2_HH + 1024 + t;
        g_Zst[base]         = __float2bfloat16(1.0f);
        g_Zst[base + KP_HH] = __float2bfloat16(0.0f);
    }
}

__global__ void trans_m1()
{
    int stride = gridDim.x * blockDim.x;
    const int total = BB * KP_M1;
    for (int i = blockIdx.x * blockDim.x + threadIdx.x; i < total; i += stride) {
        int b = i / KP_M1, j = i % KP_M1;
        float v = (j < G4) ? g_C1[(size_t)j * BB + b] : 0.f;
        __nv_bfloat16 hi, lo; split_bf16(v, hi, lo);
        size_t base = (size_t)b * K2_M1 + j;
        g_M1st[base]         = hi;
        g_M1st[base + KP_M1] = lo;
    }
}

__global__ void softmax_dim0(float* __restrict__ out)
{
    __shared__ float red[BB];
    int j = blockIdx.x;          // 0..999
    int b = threadIdx.x;         // 0..255
    float v = g_C2[(size_t)j * BB + b];
    red[b] = v;
    __syncthreads();
    for (int s = 128; s > 0; s >>= 1) {
        if (b < s) red[b] = fmaxf(red[b], red[b + s]);
        __syncthreads();
    }
    float mx = red[0];
    __syncthreads();
    float e = expf(v - mx);
    red[b] = e;
    __syncthreads();
    for (int s = 128; s > 0; s >>= 1) {
        if (b < s) red[b] += red[b + s];
        __syncthreads();
    }
    out[(size_t)b * HH + j] = e / red[0];
}

__global__ void copy_states(float* __restrict__ out)
{
    int idx = blockIdx.x * blockDim.x + threadIdx.x;
    if (idx >= BB * HH) return;
    out[256000 + idx]  = g_h1f[idx];
    out[512000 + idx]  = g_c1[idx];
    out[768000 + idx]  = g_h2f[idx];
    out[1024000 + idx] = g_c2[idx];
}

// ---------------------------------------------------------------------------
// Launch (graph-capturable)
// ---------------------------------------------------------------------------
extern "C" void kernel_launch(void* const* d_in, const int* in_sizes, int n_in,
                              void* d_out, int out_size)
{
    const float* input = (const float*)d_in[0];
    const int*   h     = (const int*)  d_in[1];
    const float* W_ih1 = (const float*)d_in[2];
    const float* W_hh1 = (const float*)d_in[3];
    const float* b_ih1 = (const float*)d_in[4];
    const float* b_hh1 = (const float*)d_in[5];
    const float* W_ih2 = (const float*)d_in[6];
    const float* W_hh2 = (const float*)d_in[7];
    const float* b_ih2 = (const float*)d_in[8];
    const float* b_hh2 = (const float*)d_in[9];
    const float* W1    = (const float*)d_in[10];
    const float* b1    = (const float*)d_in[11];
    const float* W2    = (const float*)d_in[12];
    const float* b2    = (const float*)d_in[13];
    float* out = (float*)d_out;

    __nv_bfloat16 *Wxst, *A1st, *Acatst, *W1st, *W2st, *Xst, *Zst, *M1st;
    float *X1, *C1, *C2;
    cudaGetSymbolAddress((void**)&Wxst,   g_Wxst);
    cudaGetSymbolAddress((void**)&A1st,   g_A1st);
    cudaGetSymbolAddress((void**)&Acatst, g_Acatst);
    cudaGetSymbolAddress((void**)&W1st,   g_W1st);
    cudaGetSymbolAddress((void**)&W2st,   g_W2st);
    cudaGetSymbolAddress((void**)&Xst,    g_Xst);
    cudaGetSymbolAddress((void**)&Zst,    g_Zst);
    cudaGetSymbolAddress((void**)&M1st,   g_M1st);
    cudaGetSymbolAddress((void**)&X1,     g_X1);
    cudaGetSymbolAddress((void**)&C1,     g_C1);
    cudaGetSymbolAddress((void**)&C2,     g_C2);

    const int SMEM = 2 * ((256 + 128) * 144);   // 110,592 B
    cudaFuncSetAttribute(mma_gemm<0>, cudaFuncAttributeMaxDynamicSharedMemorySize, SMEM);
    cudaFuncSetAttribute(lstm_persist, cudaFuncAttributeMaxDynamicSharedMemorySize, SMEM);

    // --- prep ---
    init_bar<<<1, 1>>>();
    prep_bias<<<16, 256>>>(b_ih1, b_hh1, b_ih2, b_hh2);
    zero_state<<<2048, 256>>>();
    cvt_x<<<8192, 256>>>(input);
    cvt_weight<<<4096, 256>>>(W_ih1, 1600, nullptr, 0, Wxst, KP_X, 0, KP_X, INS, G4, MP, 1);
    cvt_weight<<<4096, 256>>>(W_ih1 + 600, 1600, W_hh1, 1000, A1st, KP_H1, 0, 1024, 1000, G4, MP, 1);
    cvt_weight<<<4096, 256>>>(W_ih2 + 600, 2600, nullptr, 0, Acatst, KP_HH, 0, 1024, 1000, G4, MP, 1);
    cvt_weight<<<4096, 256>>>(W_ih2 + 1600, 2600, W_hh2, 1000, Acatst, KP_HH, 1024, 1024, 1000, G4, MP, 1);
    cvt_weight<<<4096, 256>>>(W1, 2000, nullptr, 0, W1st, KP_HH, 0, 1024, 1000, G4, MP, 0);
    cvt_weight<<<4096, 256>>>(W1 + 1000, 2000, nullptr, 0, W1st, KP_HH, 1024, 1024, 1000, G4, MP, 0);
    cvt_weight<<<4096, 256>>>(W2, 4000, nullptr, 0, W2st, KP_M1, 0, KP_M1, G4, 1000, 1024, 0);

    // --- prologue: X1[perm_row, t*256+b] = W_x @ x^T ---
    mma_gemm<0><<<dim3(32, 256), 256, SMEM>>>(Wxst, Xst, K2_X, MP, X1, NX, nullptr);

    // --- recurrence: single persistent kernel ---
    lstm_persist<<<NCTA, 256, SMEM>>>();

    // --- epilogue ---
    build_z<<<2048, 256>>>();
    scatter_topic<<<5, 256>>>(h);
    mma_gemm<0><<<dim3(32, 4), 256, SMEM>>>(W1st, Zst, K2_HH, G4, C1, BB, b1);
    trans_m1<<<4096, 256>>>();
    mma_gemm<0><<<dim3(8, 4), 256, SMEM>>>(W2st, M1st, K2_M1, HH, C2, BB, b2);
    softmax_dim0<<<1000, 256>>>(out);
    copy_states<<<1000, 256>>>(out);
}